// round 17
// baseline (speedup 1.0000x reference)
#include <cuda_runtime.h>
#include <cuda_fp16.h>
#include <cstdint>
#include <cstddef>

#define E_EDGES 320000
#define N_NODES 20000
#define N_RBF   20
#define TILE_E  64
#define NTILES  5000
#define OUT_S_OFF ((size_t)N_NODES * 3 * 128)
#define PITCH   136
#define WPITCH  40

typedef unsigned long long ull;

// ---- device scratch ----
__device__ __half  g_msg[(size_t)E_EDGES * 384];
__device__ int     g_hist[N_NODES];
__device__ int     g_cursor[N_NODES];
__device__ int     g_off[N_NODES + 1];
__device__ int     g_elist[E_EDGES];
__device__ double  g_sumsq;

// ---- tensor-core primitives ----
__device__ __forceinline__ void mma_f16(float* d, uint32_t a0, uint32_t a1,
                                        uint32_t a2, uint32_t a3,
                                        uint32_t b0, uint32_t b1) {
    asm volatile(
        "mma.sync.aligned.m16n8k16.row.col.f32.f16.f16.f32 "
        "{%0,%1,%2,%3}, {%4,%5,%6,%7}, {%8,%9}, {%0,%1,%2,%3};"
        : "+f"(d[0]), "+f"(d[1]), "+f"(d[2]), "+f"(d[3])
        : "r"(a0), "r"(a1), "r"(a2), "r"(a3), "r"(b0), "r"(b1));
}
__device__ __forceinline__ void ldsm4(uint32_t& r0, uint32_t& r1,
                                      uint32_t& r2, uint32_t& r3, uint32_t a) {
    asm volatile("ldmatrix.sync.aligned.m8n8.x4.shared.b16 {%0,%1,%2,%3}, [%4];"
                 : "=r"(r0), "=r"(r1), "=r"(r2), "=r"(r3) : "r"(a));
}
__device__ __forceinline__ uint32_t smem_u32(const void* p) {
    uint32_t a;
    asm("{ .reg .u64 t; cvta.to.shared.u64 t, %1; cvt.u32.u64 %0, t; }"
        : "=r"(a) : "l"(p));
    return a;
}
__device__ __forceinline__ uint32_t h2u(__half2 h) {
    return *reinterpret_cast<uint32_t*>(&h);
}

// smem byte offsets
#define OFF_B    0                 // 384*136*2 = 104448
#define OFF_WW   104448            // 384*40*2 = 30720
#define OFF_A0   135168            // 64*136*2 = 17408
#define OFF_A1   152576
#define OFF_RB0  169984            // 64*40*2 = 5120
#define OFF_RB1  175104
#define OFF_BPHI 180224            // fp32 384
#define OFF_BW   181760
#define OFF_WBUF 183296            // 12 * 512 * 4 = 24576 (w spill, [i][tid])
#define SMEM_SZ  207872

// ---- CSR/misc kernels ----
__global__ void reset_kernel() {
    int i = blockIdx.x * blockDim.x + threadIdx.x;
    if (i == 0) g_sumsq = 0.0;
    int st = gridDim.x * blockDim.x;
    for (int j = i; j < N_NODES; j += st) g_hist[j] = 0;
}
__global__ void hist_sumsq_kernel(const int* __restrict__ idx,
                                  const float* __restrict__ r) {
    int i = blockIdx.x * blockDim.x + threadIdx.x;
    int st = gridDim.x * blockDim.x;
    for (int e = i; e < E_EDGES; e += st) atomicAdd(&g_hist[idx[e]], 1);
    float s = 0.f;
    for (int j = i; j < E_EDGES * 3; j += st) { float x = r[j]; s += x * x; }
    #pragma unroll
    for (int o = 16; o > 0; o >>= 1) s += __shfl_down_sync(0xffffffffu, s, o);
    __shared__ float ws[8];
    if ((threadIdx.x & 31) == 0) ws[threadIdx.x >> 5] = s;
    __syncthreads();
    if (threadIdx.x < 8) {
        float t = ws[threadIdx.x];
        #pragma unroll
        for (int o = 4; o > 0; o >>= 1) t += __shfl_down_sync(0xffu, t, o);
        if (threadIdx.x == 0) atomicAdd(&g_sumsq, (double)t);
    }
}
__global__ void __launch_bounds__(1024) scan_kernel() {
    const int CH = 20;
    __shared__ int wsum[32];
    int t = threadIdx.x, lane = t & 31, w = t >> 5;
    int base = t * CH;
    int h[CH];
    int s = 0;
    #pragma unroll
    for (int i = 0; i < CH; i++) {
        int j = base + i;
        h[i] = (j < N_NODES) ? g_hist[j] : 0;
        s += h[i];
    }
    int ps = s;
    #pragma unroll
    for (int o = 1; o < 32; o <<= 1) {
        int u = __shfl_up_sync(0xffffffffu, ps, o);
        if (lane >= o) ps += u;
    }
    if (lane == 31) wsum[w] = ps;
    __syncthreads();
    if (w == 0) {
        int v = wsum[lane];
        #pragma unroll
        for (int o = 1; o < 32; o <<= 1) {
            int u = __shfl_up_sync(0xffffffffu, v, o);
            if (lane >= o) v += u;
        }
        wsum[lane] = v;
    }
    __syncthreads();
    int run = ps - s + ((w > 0) ? wsum[w - 1] : 0);
    #pragma unroll
    for (int i = 0; i < CH; i++) {
        int j = base + i;
        if (j < N_NODES) { g_off[j] = run; g_cursor[j] = run; run += h[i]; }
    }
    if (t == 1023) g_off[N_NODES] = run;
}
__global__ void fill_kernel(const int* __restrict__ idx) {
    int i = blockIdx.x * blockDim.x + threadIdx.x;
    int st = gridDim.x * blockDim.x;
    for (int e = i; e < E_EDGES; e += st)
        g_elist[atomicAdd(&g_cursor[idx[e]], 1)] = e;
}

// ---- fused GEMM: TILE_E=64, warp = 2 m-tiles x 48 cols ----
__global__ void __launch_bounds__(512, 1)
gemm_kernel(const float* __restrict__ s, const float* __restrict__ r,
            const float* __restrict__ Wphi, const float* __restrict__ bphi,
            const float* __restrict__ Ww, const float* __restrict__ bw)
{
    extern __shared__ char sm[];
    float* bphi_s = (float*)(sm + OFF_BPHI);
    float* bw_s   = (float*)(sm + OFF_BW);
    uint32_t* wbuf = (uint32_t*)(sm + OFF_WBUF);

    const int tid  = threadIdx.x;
    const int wid  = tid >> 5;
    const int lane = tid & 31;
    const int mp   = wid >> 3;
    const int nq   = wid & 7;
    const uint32_t smb = smem_u32(sm);

    // ---- one-time weights ----
    {
        __half* B_s = (__half*)(sm + OFF_B);
        __half* Ws  = (__half*)(sm + OFF_WW);
        for (int i = tid; i < 384 * 128; i += 512) {
            int n = i >> 7, k = i & 127;
            B_s[n * PITCH + k] = __float2half_rn(Wphi[k * 384 + n]);
        }
        for (int i = tid; i < 384 * 32; i += 512) {
            int n = i >> 5, k = i & 31;
            float x = (k < N_RBF) ? Ww[k * 384 + n] : 0.f;
            Ws[n * WPITCH + k] = __float2half_rn(x);
        }
        for (int i = tid; i < 384; i += 512) {
            bphi_s[i] = bphi[i];
            bw_s[i]   = bw[i];
        }
    }

    // ldmatrix per-thread components
    const int lr   = lane & 15;
    const int acol = (lane >> 4) << 3;
    const int brl  = ((lane >> 4) << 3) + (lane & 7);
    const int bk   = ((lane >> 3) & 1) << 3;

    const uint32_t aOff0 = (uint32_t)((mp * 32 + lr) * PITCH + acol) * 2;
    const uint32_t aOff1 = (uint32_t)((mp * 32 + 16 + lr) * PITCH + acol) * 2;
    const uint32_t rOff0 = (uint32_t)((mp * 32 + lr) * WPITCH + acol) * 2;
    const uint32_t rOff1 = (uint32_t)((mp * 32 + 16 + lr) * WPITCH + acol) * 2;
    const uint32_t bB = smb + OFF_B  + (uint32_t)((nq * 48 + brl) * PITCH + bk) * 2;
    const uint32_t wW = smb + OFF_WW + (uint32_t)((nq * 48 + brl) * WPITCH + bk) * 2;

    const int eL   = tid >> 3;
    const int cbL  = (tid & 7) * 16;
    const int rel  = tid >> 3;
    const int nb   = (tid & 7) * 4;
    const int epr  = lane >> 2;
    const int t4   = lane & 3;

    // ---- prefetch helper state (fp16-converted at load time) ----
    uint4 ah[2];     // 16 s-values as halves
    uint2 rbp;       // 4 rbf values as halves

    // prologue: prefetch + convert tile 0
    {
        const int eb0 = blockIdx.x * TILE_E;
        const float* p = &s[(size_t)(eb0 + eL) * 128 + cbL];
        #pragma unroll
        for (int q = 0; q < 2; q++) {
            float4 x0 = __ldg((const float4*)p + 2*q);
            float4 x1 = __ldg((const float4*)p + 2*q + 1);
            ah[q].x = h2u(__floats2half2_rn(x0.x, x0.y));
            ah[q].y = h2u(__floats2half2_rn(x0.z, x0.w));
            ah[q].z = h2u(__floats2half2_rn(x1.x, x1.y));
            ah[q].w = h2u(__floats2half2_rn(x1.z, x1.w));
        }
        float r0 = __ldg(&r[(eb0 + rel) * 3]);
        float r1 = __ldg(&r[(eb0 + rel) * 3 + 1]);
        float r2 = __ldg(&r[(eb0 + rel) * 3 + 2]);
        float rnorm = sqrtf(r0*r0 + r1*r1 + r2*r2);
        float nx[4];
        #pragma unroll
        for (int q = 0; q < 4; q++) {
            int n = nb + q;
            float x = 0.f;
            if (n < N_RBF) {
                float t = sinf((float)(n + 1) * (3.14159265358979323846f / 5.0f) * rnorm) / rnorm;
                x = (t <= 5.0f) ? 0.5f * (cosf(0.62831853071795864769f * t) + 1.0f) : 0.f;
            }
            nx[q] = x;
        }
        rbp.x = h2u(__floats2half2_rn(nx[0], nx[1]));
        rbp.y = h2u(__floats2half2_rn(nx[2], nx[3]));
    }
    {
        __half* A0 = (__half*)(sm + OFF_A0);
        *(uint4*)&A0[eL * PITCH + cbL]     = ah[0];
        *(uint4*)&A0[eL * PITCH + cbL + 8] = ah[1];
        __half* R0 = (__half*)(sm + OFF_RB0);
        *(uint2*)&R0[rel * WPITCH + nb] = rbp;
    }
    __syncthreads();

    uint32_t par = 0;
    for (int tile = blockIdx.x; tile < NTILES; tile += gridDim.x) {
        const int ebase = tile * TILE_E;
        const uint32_t aBuf = smb + (par ? OFF_A1 : OFF_A0);
        const uint32_t rBuf = smb + (par ? OFF_RB1 : OFF_RB0);

        // ---- prefetch next tile (convert to fp16 immediately) ----
        {
            int nt = tile + gridDim.x; if (nt >= NTILES) nt = tile;
            const int ebn = nt * TILE_E;
            const float* p = &s[(size_t)(ebn + eL) * 128 + cbL];
            #pragma unroll
            for (int q = 0; q < 2; q++) {
                float4 x0 = __ldg((const float4*)p + 2*q);
                float4 x1 = __ldg((const float4*)p + 2*q + 1);
                ah[q].x = h2u(__floats2half2_rn(x0.x, x0.y));
                ah[q].y = h2u(__floats2half2_rn(x0.z, x0.w));
                ah[q].z = h2u(__floats2half2_rn(x1.x, x1.y));
                ah[q].w = h2u(__floats2half2_rn(x1.z, x1.w));
            }
            float r0 = __ldg(&r[(ebn + rel) * 3]);
            float r1 = __ldg(&r[(ebn + rel) * 3 + 1]);
            float r2 = __ldg(&r[(ebn + rel) * 3 + 2]);
            float rnorm = sqrtf(r0*r0 + r1*r1 + r2*r2);
            float nx[4];
            #pragma unroll
            for (int q = 0; q < 4; q++) {
                int n = nb + q;
                float x = 0.f;
                if (n < N_RBF) {
                    float t = sinf((float)(n + 1) * (3.14159265358979323846f / 5.0f) * rnorm) / rnorm;
                    x = (t <= 5.0f) ? 0.5f * (cosf(0.62831853071795864769f * t) + 1.0f) : 0.f;
                }
                nx[q] = x;
            }
            rbp.x = h2u(__floats2half2_rn(nx[0], nx[1]));
            rbp.y = h2u(__floats2half2_rn(nx[2], nx[3]));
        }

        // ---- w-GEMM ----
        float acc_w[2][6][4];
        #pragma unroll
        for (int m = 0; m < 2; m++)
            #pragma unroll
            for (int j = 0; j < 6; j++)
                acc_w[m][j][0] = acc_w[m][j][1] = acc_w[m][j][2] = acc_w[m][j][3] = 0.f;
        #pragma unroll
        for (int kk = 0; kk < 2; kk++) {
            const uint32_t ko = kk * 32;
            uint32_t a00, a01, a02, a03, a10, a11, a12, a13;
            ldsm4(a00, a01, a02, a03, rBuf + rOff0 + ko);
            ldsm4(a10, a11, a12, a13, rBuf + rOff1 + ko);
            #pragma unroll
            for (int jj = 0; jj < 3; jj++) {
                const uint32_t bo = (uint32_t)(jj * 16 * WPITCH) * 2 + ko;
                uint32_t h0, h1, h2, h3;
                ldsm4(h0, h1, h2, h3, wW + bo);
                mma_f16(acc_w[0][2*jj],   a00, a01, a02, a03, h0, h1);
                mma_f16(acc_w[0][2*jj+1], a00, a01, a02, a03, h2, h3);
                mma_f16(acc_w[1][2*jj],   a10, a11, a12, a13, h0, h1);
                mma_f16(acc_w[1][2*jj+1], a10, a11, a12, a13, h2, h3);
            }
        }
        // fold bw, pack; keep m=0 in regs, spill m=1 to smem ([i][tid])
        uint32_t wp0[6][2];
        #pragma unroll
        for (int j = 0; j < 6; j++) {
            int cj = nq * 48 + j * 8 + t4 * 2;
            float b0 = bw_s[cj], b1 = bw_s[cj + 1];
            wp0[j][0] = h2u(__floats2half2_rn(acc_w[0][j][0] + b0, acc_w[0][j][1] + b1));
            wp0[j][1] = h2u(__floats2half2_rn(acc_w[0][j][2] + b0, acc_w[0][j][3] + b1));
            wbuf[(j * 2    ) * 512 + tid] =
                h2u(__floats2half2_rn(acc_w[1][j][0] + b0, acc_w[1][j][1] + b1));
            wbuf[(j * 2 + 1) * 512 + tid] =
                h2u(__floats2half2_rn(acc_w[1][j][2] + b0, acc_w[1][j][3] + b1));
        }

        // ---- main GEMM ----
        float acc[2][6][4];
        #pragma unroll
        for (int m = 0; m < 2; m++)
            #pragma unroll
            for (int j = 0; j < 6; j++)
                acc[m][j][0] = acc[m][j][1] = acc[m][j][2] = acc[m][j][3] = 0.f;
        #pragma unroll 4
        for (int kk = 0; kk < 8; kk++) {
            const uint32_t ko = kk * 32;
            uint32_t a00, a01, a02, a03, a10, a11, a12, a13;
            ldsm4(a00, a01, a02, a03, aBuf + aOff0 + ko);
            ldsm4(a10, a11, a12, a13, aBuf + aOff1 + ko);
            #pragma unroll
            for (int jj = 0; jj < 3; jj++) {
                const uint32_t bo = (uint32_t)(jj * 16 * PITCH) * 2 + ko;
                uint32_t h0, h1, h2, h3;
                ldsm4(h0, h1, h2, h3, bB + bo);
                mma_f16(acc[0][2*jj],   a00, a01, a02, a03, h0, h1);
                mma_f16(acc[0][2*jj+1], a00, a01, a02, a03, h2, h3);
                mma_f16(acc[1][2*jj],   a10, a11, a12, a13, h0, h1);
                mma_f16(acc[1][2*jj+1], a10, a11, a12, a13, h2, h3);
            }
        }

        // ---- epilogue: direct STG.64 (m=0 from regs, m=1 from wbuf) ----
        #pragma unroll
        for (int m = 0; m < 2; m++) {
            const int er0 = ebase + mp * 32 + m * 16 + epr;
            __half* row0 = &g_msg[(size_t)er0 * 384];
            __half* row1 = &g_msg[(size_t)(er0 + 8) * 384];
            #pragma unroll
            for (int j = 0; j < 6; j++) {
                int cj = nq * 48 + j * 8 + t4 * 2;
                float b0 = bphi_s[cj], b1 = bphi_s[cj + 1];
                uint32_t u0 = (m == 0) ? wp0[j][0] : wbuf[(j * 2    ) * 512 + tid];
                uint32_t u1 = (m == 0) ? wp0[j][1] : wbuf[(j * 2 + 1) * 512 + tid];
                float2 w0 = __half22float2(*reinterpret_cast<__half2*>(&u0));
                float2 w1 = __half22float2(*reinterpret_cast<__half2*>(&u1));
                __half2 q0 = __floats2half2_rn(w0.x * (acc[m][j][0] + b0),
                                               w0.y * (acc[m][j][1] + b1));
                __half2 q1 = __floats2half2_rn(w1.x * (acc[m][j][2] + b0),
                                               w1.y * (acc[m][j][3] + b1));
                *(uint32_t*)(row0 + cj) = h2u(q0);
                *(uint32_t*)(row1 + cj) = h2u(q1);
            }
        }

        // ---- stage next tile into the OTHER buffer ----
        {
            __half* An = (__half*)(sm + (par ? OFF_A0 : OFF_A1));
            *(uint4*)&An[eL * PITCH + cbL]     = ah[0];
            *(uint4*)&An[eL * PITCH + cbL + 8] = ah[1];
            __half* Rn = (__half*)(sm + (par ? OFF_RB0 : OFF_RB1));
            *(uint2*)&Rn[rel * WPITCH + nb] = rbp;
        }
        __syncthreads();
        par ^= 1;
    }
}

// ---- per-node gather (unchanged) ----
__global__ void __launch_bounds__(128)
gather_kernel(const float* __restrict__ r, const float* __restrict__ v,
              float* __restrict__ out)
{
    const int n = blockIdx.x;
    const int f = threadIdx.x;
    const float ginv = (float)(1.0 / sqrt(g_sumsq));
    const int beg = g_off[n], end = g_off[n + 1];

    float a0 = 0.f, a1 = 0.f, a2 = 0.f, as = 0.f;
    int p = beg;

    int e[4];
    bool have = (p + 4 <= end);
    if (have) {
        #pragma unroll
        for (int q = 0; q < 4; q++) e[q] = g_elist[p + q];
    }
    #pragma unroll 1
    while (have) {
        int en[4];
        bool haven = (p + 8 <= end);
        if (haven) {
            #pragma unroll
            for (int q = 0; q < 4; q++) en[q] = g_elist[p + 4 + q];
        }
        #pragma unroll
        for (int q = 0; q < 4; q++) {
            const __half* m  = &g_msg[(size_t)e[q] * 384];
            const float*  vp = &v[(size_t)e[q] * 384];
            float sp0 = __half2float(m[f]);
            float sp1 = __half2float(m[128 + f]);
            float sp2 = __half2float(m[256 + f]);
            float v0 = vp[f], v1 = vp[128 + f], v2 = vp[256 + f];
            float r0 = __ldg(&r[e[q] * 3]);
            float r1 = __ldg(&r[e[q] * 3 + 1]);
            float r2 = __ldg(&r[e[q] * 3 + 2]);
            a0 += sp2 * (r0 * ginv) + sp0 * v0;
            a1 += sp2 * (r1 * ginv) + sp0 * v1;
            a2 += sp2 * (r2 * ginv) + sp0 * v2;
            as += sp1;
        }
        p += 4;
        have = haven;
        #pragma unroll
        for (int q = 0; q < 4; q++) e[q] = en[q];
    }
    #pragma unroll 1
    for (; p < end; p++) {
        const int eo = g_elist[p];
        const __half* m  = &g_msg[(size_t)eo * 384];
        const float*  vp = &v[(size_t)eo * 384];
        float sp0 = __half2float(m[f]);
        float sp1 = __half2float(m[128 + f]);
        float sp2 = __half2float(m[256 + f]);
        float r0 = __ldg(&r[eo * 3]), r1 = __ldg(&r[eo * 3 + 1]), r2 = __ldg(&r[eo * 3 + 2]);
        a0 += sp2 * (r0 * ginv) + sp0 * vp[f];
        a1 += sp2 * (r1 * ginv) + sp0 * vp[128 + f];
        a2 += sp2 * (r2 * ginv) + sp0 * vp[256 + f];
        as += sp1;
    }
    size_t ob = (size_t)n * 384;
    out[ob + f]       = a0;
    out[ob + 128 + f] = a1;
    out[ob + 256 + f] = a2;
    out[OUT_S_OFF + (size_t)n * 128 + f] = as;
}

extern "C" void kernel_launch(void* const* d_in, const int* in_sizes, int n_in,
                              void* d_out, int out_size) {
    const float* s    = (const float*)d_in[0];
    const float* r    = (const float*)d_in[1];
    const float* v    = (const float*)d_in[2];
    const int*   idx  = (const int*)d_in[3];
    const float* Wphi = (const float*)d_in[4];
    const float* bphi = (const float*)d_in[5];
    const float* Ww   = (const float*)d_in[6];
    const float* bw   = (const float*)d_in[7];
    float* out = (float*)d_out;

    static cudaStream_t s2 = nullptr;
    static cudaEvent_t evFork = nullptr, evJoin = nullptr;
    if (s2 == nullptr) {
        cudaStreamCreateWithFlags(&s2, cudaStreamNonBlocking);
        cudaEventCreateWithFlags(&evFork, cudaEventDisableTiming);
        cudaEventCreateWithFlags(&evJoin, cudaEventDisableTiming);
    }

    cudaEventRecord(evFork, 0);
    cudaStreamWaitEvent(s2, evFork, 0);

    reset_kernel<<<64, 256, 0, s2>>>();
    hist_sumsq_kernel<<<256, 256, 0, s2>>>(idx, r);
    scan_kernel<<<1, 1024, 0, s2>>>();

    // gemm at launch index 3 (ncu profiles the 4th launch)
    cudaFuncSetAttribute(gemm_kernel,
                         cudaFuncAttributeMaxDynamicSharedMemorySize, SMEM_SZ);
    gemm_kernel<<<148, 512, SMEM_SZ>>>(s, r, Wphi, bphi, Ww, bw);

    fill_kernel<<<256, 256, 0, s2>>>(idx);
    cudaEventRecord(evJoin, s2);

    cudaStreamWaitEvent(0, evJoin, 0);
    gather_kernel<<<N_NODES, 128>>>(r, v, out);
}